// round 15
// baseline (speedup 1.0000x reference)
#include <cuda_runtime.h>
#include <cuda_fp16.h>

// FastRotation — persistent-warp half2 pair tile, v9 (inner body = R14).
// Each warp grabs volumes in a grid-stride loop. The tile's zero borders are
// volume-invariant (staging rewrites exactly the same 250 interior halves
// every volume and never touches border words), so the zero-fill happens
// ONCE per warp lifetime instead of once per volume — removing ~13% of the
// saturated L1 pipe's wavefronts — and the tiny fixed grid (8 blocks/SM
// exactly) removes wave-transition bubbles.
// Tile: slot (z,y,xp) at word 49z+7y+xp+56 holds fp16 x-pair
// (v[z][y][xp-1], v[z][y][xp]); z,y in [-1..5], xp in [0..5]; borders zero.

#define KVOL  125
#define ZSTR  49          // words per z-slab (7 rows * 7 words)
#define YSTR  7           // words per row
#define WORDS 344         // 343 padded to float4 multiple
#define WPB   8           // warps per block
#define TPB   (WPB * 32)
#define GRID_BLOCKS 1184  // 148 SMs * 8 resident 256-thread blocks

// fp16 bit patterns for lattice coord c = 0.5*idx - 1, idx in 0..4
#define HP(i) ((i)==0 ? 0xBC00u : (i)==1 ? 0xB800u : (i)==2 ? 0x0000u : \
               (i)==3 ? 0x3800u : 0x3C00u)
// Packed base for point p = i*25 + j*5 + l : u.x = half(bi)|half(bj)<<16, u.y = half(bl)
#define UV(i,j,l) { HP(i) | (HP(j) << 16), HP(l) }
#define U5(i,j)  UV(i,j,0), UV(i,j,1), UV(i,j,2), UV(i,j,3), UV(i,j,4)
#define U25(i)   U5(i,0), U5(i,1), U5(i,2), U5(i,3), U5(i,4)
__device__ const uint2 g_bh[128] = { U25(0), U25(1), U25(2), U25(3), U25(4) };

__global__ __launch_bounds__(TPB) void fast_rotation_kernel(
    const float* __restrict__ vol,      // [N,125]
    const float* __restrict__ theta_v,  // [N,3]
    const float* __restrict__ theta,    // [N]
    float* __restrict__ out,            // [N,125]
    int N)
{
    __shared__ __half2 sp[WPB * WORDS];

    const int w    = threadIdx.x >> 5;
    const int lane = threadIdx.x & 31;

    __half2* tile  = &sp[w * WORDS];
    __half*  tileh = (__half*)tile;

    // One-time zero-fill of the whole tile (borders stay zero forever;
    // interior halves are rewritten by staging every volume).
    {
        float4* t4 = (float4*)tile;
        const float4 z4 = make_float4(0.f, 0.f, 0.f, 0.f);
        t4[lane]      = z4;
        t4[lane + 32] = z4;
        if (lane < 86 - 64) t4[lane + 64] = z4;
    }
    __syncwarp();

    const int warpId     = blockIdx.x * WPB + w;
    const int totalWarps = gridDim.x * WPB;

    for (int n = warpId; n < N; n += totalWarps) {
        // Hoist rotation params (broadcast loads overlap staging)
        const float tx = theta_v[n * 3 + 0];
        const float ty = theta_v[n * 3 + 1];
        const float tz = theta_v[n * 3 + 2];
        const float th = theta[n];

        // Stage volume: element m = z*25+y*5+x -> halves 2b+1 (.y of word b)
        // and 2b+2 (.x of word b+1), b = 49z+7y+x+56. Branch-free decode.
        const float* vsrc = vol + n * KVOL;
        #pragma unroll
        for (int q = 0; q < 4; ++q) {
            const int m = lane + 32 * q;
            if (m < KVOL) {
                const __half h = __float2half_rn(__ldcs(vsrc + m));
                const int z   = (m * 41) >> 10;       // m / 25
                const int rem = m - 25 * z;
                const int y   = (rem * 205) >> 10;    // rem / 5
                const int x   = rem - 5 * y;
                const int b   = 49 * z + 7 * y + x + 56;
                tileh[2 * b + 1] = h;
                tileh[2 * b + 2] = h;
            }
        }

        // Rodrigues matrix (pre-scaled by 2), redundant per lane. |v|^2 == 1.
        const float inv = rsqrtf(fmaxf(tx * tx + ty * ty + tz * tz, 1e-24f));
        const float vx = tx * inv, vy = ty * inv, vz = tz * inv;
        const float ss = 2.0f * __sinf(th);
        const float cs = 2.0f * (1.0f - __cosf(th));
        const float R00 = 2.0f + cs * (vx * vx - 1.0f);
        const float R01 = -ss * vz + cs * (vx * vy);
        const float R02 =  ss * vy + cs * (vx * vz);
        const float R10 =  ss * vz + cs * (vy * vx);
        const float R11 = 2.0f + cs * (vy * vy - 1.0f);
        const float R12 = -ss * vx + cs * (vy * vz);
        const float R20 = -ss * vy + cs * (vz * vx);
        const float R21 =  ss * vx + cs * (vz * vy);
        const float R22 = 2.0f + cs * (vz * vz - 1.0f);

        __syncwarp();   // staging visible warp-wide

        float* dst = out + n * KVOL;

        #pragma unroll
        for (int q = 0; q < 4; ++q) {
            const int p = lane + 32 * q;
            if (p < KVOL) {
                const uint2 u = __ldg(&g_bh[p]);
                const __half2 hij = *reinterpret_cast<const __half2*>(&u.x);
                const float2 bij  = __half22float2(hij);
                const float  bl   = __half2float(*reinterpret_cast<const __half*>(&u.y));

                // pixel coords: (grid + 1) * 2 = base . (2R) + 2
                const float x = fmaf(bij.x, R00, fmaf(bij.y, R10, fmaf(bl, R20, 2.0f)));
                const float y = fmaf(bij.x, R01, fmaf(bij.y, R11, fmaf(bl, R21, 2.0f)));
                const float z = fmaf(bij.x, R02, fmaf(bij.y, R12, fmaf(bl, R22, 2.0f)));

                const int x0 = __float2int_rd(x);
                const int y0 = __float2int_rd(y);
                const int z0 = __float2int_rd(z);
                const float wx = x - (float)x0;
                const float wy = y - (float)y0;
                const float wz = z - (float)z0;

                // In-range iff base cell in [-1,4] per axis; else exact zero.
                const bool ok = ((unsigned)(x0 + 1) <= 5u) &
                                ((unsigned)(y0 + 1) <= 5u) &
                                ((unsigned)(z0 + 1) <= 5u);

                float r = 0.0f;
                if (ok) {
                    // slot (z0,y0,x0+1): word = 49*z0 + 7*y0 + x0 + 57
                    const int wd = z0 * ZSTR + y0 * YSTR + x0 + (ZSTR + YSTR + 1);
                    const __half2 f00 = tile[wd];
                    const __half2 f10 = tile[wd + YSTR];
                    const __half2 f01 = tile[wd + ZSTR];
                    const __half2 f11 = tile[wd + ZSTR + YSTR];

                    const __half2 wyb = __float2half2_rn(wy);
                    const __half2 wzb = __float2half2_rn(wz);

                    const __half2 a0 = __hfma2(__hsub2(f10, f00), wyb, f00);
                    const __half2 a1 = __hfma2(__hsub2(f11, f01), wyb, f01);
                    const __half2 g  = __hfma2(__hsub2(a1, a0), wzb, a0);

                    const float2 gf = __half22float2(g);
                    r = fmaf(wx, gf.y - gf.x, gf.x);
                }
                dst[p] = r;
            }
        }

        __syncwarp();   // all lanes done sampling before next volume restages
    }
}

extern "C" void kernel_launch(void* const* d_in, const int* in_sizes, int n_in,
                              void* d_out, int out_size)
{
    const float* vol     = (const float*)d_in[0];  // input_filter [N,5,5,5]
    const float* theta_v = (const float*)d_in[1];  // [N,3]
    const float* theta   = (const float*)d_in[2];  // [N]
    float* out = (float*)d_out;

    const int N = in_sizes[2];                     // theta has N elements
    const int needed = (N + WPB - 1) / WPB;
    const int blocks = needed < GRID_BLOCKS ? needed : GRID_BLOCKS;
    fast_rotation_kernel<<<blocks, TPB>>>(vol, theta_v, theta, out, N);
}